// round 2
// baseline (speedup 1.0000x reference)
#include <cuda_runtime.h>
#include <cstddef>

// Problem constants (match reference)
#define NROWS 32768
#define DDIM  64
#define RRULE 32
#define EPSF  1e-12f

#define WARPS_PER_BLOCK 8
#define ROWS_PER_WARP   4
#define THREADS (WARPS_PER_BLOCK * 32)
#define NBLOCKS (NROWS / (WARPS_PER_BLOCK * ROWS_PER_WARP))  // 1024
#define PSTRIDE 33   // padded [d][r] stride to kill STS bank conflicts

// Output layout (flattened tuple): y[N] | w[N*R] | Phi[N*R*(D+1)]
#define OFF_W   ((size_t)NROWS)
#define OFF_PHI ((size_t)NROWS + (size_t)NROWS * RRULE)
#define PHI_ROW (RRULE * (DDIM + 1))          // 2080 floats
#define PHI_VEC (PHI_ROW / 4)                 // 520 float4 per row
#define PHI_ITERS ((PHI_VEC + 31) / 32)       // 17 j-iterations

__global__ __launch_bounds__(THREADS)
void tsk_kernel(const float* __restrict__ Xz,
                const float* __restrict__ C,
                const float* __restrict__ S,
                const float* __restrict__ Th,
                float* __restrict__ out)
{
    __shared__ float c_sh [DDIM * PSTRIDE];
    __shared__ float is_sh[DDIM * PSTRIDE];
    __shared__ float th_sh[DDIM * PSTRIDE];
    __shared__ float tb_sh[RRULE];
    __shared__ float x1_sh[WARPS_PER_BLOCK][ROWS_PER_WARP][DDIM + 2]; // [0]=1, [1..64]=x
    __shared__ float ws_sh[WARPS_PER_BLOCK][ROWS_PER_WARP][RRULE];

    const int tid = threadIdx.x;

    // ---- load params into shared, transposed to [d][r] ----
    for (int i = tid; i < RRULE * DDIM; i += THREADS) {
        int r = i / DDIM, d = i % DDIM;
        c_sh [d * PSTRIDE + r] = C[i];
        is_sh[d * PSTRIDE + r] = 1.0f / (S[i] + EPSF);
    }
    for (int i = tid; i < RRULE * (DDIM + 1); i += THREADS) {
        int r = i / (DDIM + 1), k = i % (DDIM + 1);
        if (k == 0) tb_sh[r] = Th[i];
        else        th_sh[(k - 1) * PSTRIDE + r] = Th[i];
    }

    const int warp = tid >> 5;
    const int lane = tid & 31;
    const int gw   = blockIdx.x * WARPS_PER_BLOCK + warp;
    const int row0 = gw * ROWS_PER_WARP;

    // ---- load 4 consecutive rows of x into x1 (leading 1 per row) ----
    {
        const float* xg = Xz + (size_t)row0 * DDIM;   // 256 contiguous floats
        #pragma unroll
        for (int i = 0; i < 8; i++) {
            int idx = i * 32 + lane;                  // 0..255, coalesced
            int q = idx >> 6, d = idx & 63;
            x1_sh[warp][q][1 + d] = xg[idx];
        }
        if (lane < ROWS_PER_WARP) x1_sh[warp][lane][0] = 1.0f;
    }
    __syncthreads();

    // ---- main loop: per-lane rule, 4 rows at once ----
    float acc0 = 0.f, acc1 = 0.f, acc2 = 0.f, acc3 = 0.f;
    const float tb = tb_sh[lane];
    float t0 = tb, t1 = tb, t2 = tb, t3 = tb;

    #pragma unroll 8
    for (int d = 0; d < DDIM; d++) {
        const float c  = c_sh [d * PSTRIDE + lane];
        const float is = is_sh[d * PSTRIDE + lane];
        const float th = th_sh[d * PSTRIDE + lane];
        float x, z;
        x = x1_sh[warp][0][d + 1]; z = (x - c) * is; acc0 = fmaf(z, z, acc0); t0 = fmaf(th, x, t0);
        x = x1_sh[warp][1][d + 1]; z = (x - c) * is; acc1 = fmaf(z, z, acc1); t1 = fmaf(th, x, t1);
        x = x1_sh[warp][2][d + 1]; z = (x - c) * is; acc2 = fmaf(z, z, acc2); t2 = fmaf(th, x, t2);
        x = x1_sh[warp][3][d + 1]; z = (x - c) * is; acc3 = fmaf(z, z, acc3); t3 = fmaf(th, x, t3);
    }

    // ---- softmax + w/y outputs, per row ----
    const float accs[4] = {acc0, acc1, acc2, acc3};
    const float ts[4]   = {t0, t1, t2, t3};
    #pragma unroll
    for (int q = 0; q < ROWS_PER_WARP; q++) {
        float lw = -0.5f * accs[q];
        float mx = lw;
        #pragma unroll
        for (int o = 16; o > 0; o >>= 1)
            mx = fmaxf(mx, __shfl_xor_sync(0xFFFFFFFFu, mx, o));
        float e = __expf(lw - mx);
        float s = e;
        #pragma unroll
        for (int o = 16; o > 0; o >>= 1)
            s += __shfl_xor_sync(0xFFFFFFFFu, s, o);
        float w = e / (s + EPSF);
        ws_sh[warp][q][lane] = w;
        out[OFF_W + (size_t)(row0 + q) * RRULE + lane] = w;
        float p = w * ts[q];
        #pragma unroll
        for (int o = 16; o > 0; o >>= 1)
            p += __shfl_xor_sync(0xFFFFFFFFu, p, o);
        if (lane == 0) out[row0 + q] = p;
    }
    __syncwarp();

    // ---- Phi: float4 stores; index math shared across the 4 rows ----
    // element(idx) = w[idx/65] * x1[idx%65]; lane handles idx=base..base+3.
    float* __restrict__ phi = out + OFF_PHI + (size_t)row0 * PHI_ROW;
    #pragma unroll 1
    for (int j = 0; j < PHI_ITERS; j++) {
        const int v = j * 32 + lane;                // float4 index within row
        if (v < PHI_VEC) {
            const int base = v * 4;
            const unsigned r0 = (unsigned)base / 65u;
            const int k0 = base - (int)r0 * 65;
            #pragma unroll
            for (int q = 0; q < ROWS_PER_WARP; q++) {
                const float* __restrict__ xp = &x1_sh[warp][q][0];
                const float* __restrict__ wp = &ws_sh[warp][q][0];
                const float w0 = wp[r0];
                float vals[4];
                #pragma unroll
                for (int i = 0; i < 4; i++) {
                    int k = k0 + i;
                    float wv = w0;
                    if (k >= 65) { k -= 65; wv = wp[r0 + 1]; }  // wrap: only if k0>=62, r0<=30
                    vals[i] = wv * xp[k];
                }
                float4 o4 = make_float4(vals[0], vals[1], vals[2], vals[3]);
                __stcs((float4*)&phi[(size_t)q * PHI_ROW + base], o4);
            }
        }
    }
}

extern "C" void kernel_launch(void* const* d_in, const int* in_sizes, int n_in,
                              void* d_out, int out_size)
{
    const float* Xz = (const float*)d_in[0];
    const float* C  = (const float*)d_in[1];
    const float* S  = (const float*)d_in[2];
    const float* Th = (const float*)d_in[3];
    float* out = (float*)d_out;
    (void)in_sizes; (void)n_in; (void)out_size;
    tsk_kernel<<<NBLOCKS, THREADS>>>(Xz, C, S, Th, out);
}

// round 3
// speedup vs baseline: 1.1197x; 1.1197x over previous
#include <cuda_runtime.h>
#include <cstddef>

#define NROWS 32768
#define DDIM  64
#define RRULE 32
#define EPSF  1e-12f

#define WARPS_PER_BLOCK 8
#define ROWS_PER_WARP   4
#define THREADS (WARPS_PER_BLOCK * 32)
#define NBLOCKS (NROWS / (WARPS_PER_BLOCK * ROWS_PER_WARP))  // 1024
#define PSTRIDE 33

#define OFF_W   ((size_t)NROWS)
#define OFF_PHI ((size_t)NROWS + (size_t)NROWS * RRULE)
#define PHI_ROW (RRULE * (DDIM + 1))          // 2080 floats
#define PHI_VEC (PHI_ROW / 4)                 // 520 float4 per row
#define WSPAD   36                            // padded w row (r0+1 can reach 34 on masked lanes)

__global__ __launch_bounds__(THREADS)
void tsk_kernel(const float* __restrict__ Xz,
                const float* __restrict__ C,
                const float* __restrict__ S,
                const float* __restrict__ Th,
                float* __restrict__ out)
{
    __shared__ float c_sh [DDIM * PSTRIDE];
    __shared__ float is_sh[DDIM * PSTRIDE];
    __shared__ float th_sh[DDIM * PSTRIDE];
    __shared__ float tb_sh[RRULE];
    __shared__ float x1_sh[WARPS_PER_BLOCK][ROWS_PER_WARP][DDIM + 2]; // [0]=1, [1..64]=x
    __shared__ float ws_sh[WARPS_PER_BLOCK][ROWS_PER_WARP][WSPAD];

    const int tid = threadIdx.x;

    // ---- params to shared, transposed [d][r] ----
    for (int i = tid; i < RRULE * DDIM; i += THREADS) {
        int r = i / DDIM, d = i % DDIM;
        c_sh [d * PSTRIDE + r] = C[i];
        is_sh[d * PSTRIDE + r] = 1.0f / (S[i] + EPSF);
    }
    for (int i = tid; i < RRULE * (DDIM + 1); i += THREADS) {
        int r = i / (DDIM + 1), k = i % (DDIM + 1);
        if (k == 0) tb_sh[r] = Th[i];
        else        th_sh[(k - 1) * PSTRIDE + r] = Th[i];
    }

    const int warp = tid >> 5;
    const int lane = tid & 31;
    const int gw   = blockIdx.x * WARPS_PER_BLOCK + warp;
    const int row0 = gw * ROWS_PER_WARP;

    // ---- 4 rows of x into x1 (leading 1 per row) ----
    {
        const float* xg = Xz + (size_t)row0 * DDIM;
        #pragma unroll
        for (int i = 0; i < 8; i++) {
            int idx = i * 32 + lane;
            int q = idx >> 6, d = idx & 63;
            x1_sh[warp][q][1 + d] = xg[idx];
        }
        if (lane < ROWS_PER_WARP) x1_sh[warp][lane][0] = 1.0f;
        if (lane < ROWS_PER_WARP * 4) {          // zero the w padding [32..35]
            int q = lane >> 2;
            ws_sh[warp][q][RRULE + (lane & 3)] = 0.0f;
        }
    }
    __syncthreads();

    // ---- membership + affine accumulators (lane = rule) ----
    float acc0 = 0.f, acc1 = 0.f, acc2 = 0.f, acc3 = 0.f;
    const float tb = tb_sh[lane];
    float t0 = tb, t1 = tb, t2 = tb, t3 = tb;

    #pragma unroll 8
    for (int d = 0; d < DDIM; d++) {
        const float c  = c_sh [d * PSTRIDE + lane];
        const float is = is_sh[d * PSTRIDE + lane];
        const float th = th_sh[d * PSTRIDE + lane];
        float x, z;
        x = x1_sh[warp][0][d + 1]; z = (x - c) * is; acc0 = fmaf(z, z, acc0); t0 = fmaf(th, x, t0);
        x = x1_sh[warp][1][d + 1]; z = (x - c) * is; acc1 = fmaf(z, z, acc1); t1 = fmaf(th, x, t1);
        x = x1_sh[warp][2][d + 1]; z = (x - c) * is; acc2 = fmaf(z, z, acc2); t2 = fmaf(th, x, t2);
        x = x1_sh[warp][3][d + 1]; z = (x - c) * is; acc3 = fmaf(z, z, acc3); t3 = fmaf(th, x, t3);
    }

    // ---- softmax + w/y outputs ----
    const float accs[4] = {acc0, acc1, acc2, acc3};
    const float ts[4]   = {t0, t1, t2, t3};
    #pragma unroll
    for (int q = 0; q < ROWS_PER_WARP; q++) {
        float lw = -0.5f * accs[q];
        float mx = lw;
        #pragma unroll
        for (int o = 16; o > 0; o >>= 1)
            mx = fmaxf(mx, __shfl_xor_sync(0xFFFFFFFFu, mx, o));
        float e = __expf(lw - mx);
        float s = e;
        #pragma unroll
        for (int o = 16; o > 0; o >>= 1)
            s += __shfl_xor_sync(0xFFFFFFFFu, s, o);
        float w = e / (s + EPSF);
        ws_sh[warp][q][lane] = w;
        out[OFF_W + (size_t)(row0 + q) * RRULE + lane] = w;
        float p = w * ts[q];
        #pragma unroll
        for (int o = 16; o > 0; o >>= 1)
            p += __shfl_xor_sync(0xFFFFFFFFu, p, o);
        if (lane == 0) out[row0 + q] = p;
    }
    __syncwarp();

    // ---- Phi: sliding register window, STG.128, no LDS of x in the loop ----
    // invariant: V[q][i] = x1_q[(k0 + i) mod 65]; element idx = 65*r + k.
    float V[ROWS_PER_WARP][4];
    int k0 = 4 * lane;
    int r0 = 0;
    if (k0 >= 65) { k0 -= 65; r0 = 1; }

    {
        int kk[4];
        #pragma unroll
        for (int i = 0; i < 4; i++) {
            int k = k0 + i;
            kk[i] = (k >= 65) ? k - 65 : k;
        }
        #pragma unroll
        for (int q = 0; q < ROWS_PER_WARP; q++) {
            #pragma unroll
            for (int i = 0; i < 4; i++)
                V[q][i] = x1_sh[warp][q][kk[i]];
        }
    }

    float* __restrict__ phi = out + OFF_PHI + (size_t)row0 * PHI_ROW;

    #pragma unroll 1
    for (int j = 0; j < 17; j++) {
        const int v = j * 32 + lane;
        const bool live = (v < PHI_VEC);
        #pragma unroll
        for (int q = 0; q < ROWS_PER_WARP; q++) {
            const float wA = ws_sh[warp][q][r0];
            const float wB = ws_sh[warp][q][r0 + 1];
            float4 o4;
            o4.x = V[q][0] * ((k0 + 0 < 65) ? wA : wB);
            o4.y = V[q][1] * ((k0 + 1 < 65) ? wA : wB);
            o4.z = V[q][2] * ((k0 + 2 < 65) ? wA : wB);
            o4.w = V[q][3] * ((k0 + 3 < 65) ? wA : wB);
            if (live)
                __stcs((float4*)&phi[(size_t)q * PHI_ROW + (size_t)v * 4], o4);
        }
        if (j < 16) {
            // slide window by -2 (mod 65)
            #pragma unroll
            for (int q = 0; q < ROWS_PER_WARP; q++) {
                float t2 = __shfl_up_sync(0xFFFFFFFFu, V[q][2], 1);
                float t3 = __shfl_up_sync(0xFFFFFFFFu, V[q][3], 1);
                float u3 = __shfl_sync(0xFFFFFFFFu, V[q][3], 15);
                float u0 = __shfl_sync(0xFFFFFFFFu, V[q][0], 16);
                float n0 = (lane == 0) ? u3 : t2;
                float n1 = (lane == 0) ? u0 : t3;
                V[q][3] = V[q][1];
                V[q][2] = V[q][0];
                V[q][0] = n0;
                V[q][1] = n1;
            }
            const int bump = (k0 >= 2) ? 2 : 1;
            const int kn   = (k0 >= 2) ? (k0 - 2) : (k0 + 63);
            r0 += bump;
            k0 = kn;
        }
    }
}

extern "C" void kernel_launch(void* const* d_in, const int* in_sizes, int n_in,
                              void* d_out, int out_size)
{
    const float* Xz = (const float*)d_in[0];
    const float* C  = (const float*)d_in[1];
    const float* S  = (const float*)d_in[2];
    const float* Th = (const float*)d_in[3];
    float* out = (float*)d_out;
    (void)in_sizes; (void)n_in; (void)out_size;
    tsk_kernel<<<NBLOCKS, THREADS>>>(Xz, C, S, Th, out);
}